// round 14
// baseline (speedup 1.0000x reference)
#include <cuda_runtime.h>
#include <cstdint>

#define NN   100000
#define EE   1600000
#define INC  256
#define HID  128
#define OUTC 64
#define SCAN_B 128
#define MAXBLK 1024

// -------- scratch (__device__ globals; allocation is forbidden) --------
static __device__ __align__(256) int   d_degi[NN];
static __device__ __align__(256) int   d_off [NN + 1];
static __device__ __align__(256) int   d_cur [NN];
static __device__ __align__(256) int   d_csr [EE];
static __device__ __align__(256) int   d_bsum [MAXBLK];
static __device__ __align__(256) int   d_bsum2[MAXBLK];
static __device__ __align__(256) float d_dinv[NN];
static __device__ __align__(256) float d_Hs [(size_t)NN * HID];  // x@W1 (unscaled)
static __device__ __align__(256) float d_H1 [(size_t)NN * HID];  // leaky(agg1)
static __device__ __align__(256) float d_Gs [(size_t)NN * HID];  // dinv*(H1@Wcat)
static __device__ __align__(256) float d_Wcat[HID * HID];

// ---------------- tf32 / async helpers ----------------
static __device__ __forceinline__ uint32_t bits2tf32(uint32_t b) {
    uint32_t r;
    asm("cvt.rna.tf32.f32 %0, %1;" : "=r"(r) : "f"(__uint_as_float(b)));
    return r;
}
static __device__ __forceinline__ void mma_tf32_16x8x8(
    float& c0, float& c1, float& c2, float& c3,
    uint32_t a0, uint32_t a1, uint32_t a2, uint32_t a3,
    uint32_t b0, uint32_t b1) {
    asm volatile(
        "mma.sync.aligned.m16n8k8.row.col.f32.tf32.tf32.f32 "
        "{%0,%1,%2,%3}, {%4,%5,%6,%7}, {%8,%9}, {%0,%1,%2,%3};"
        : "+f"(c0), "+f"(c1), "+f"(c2), "+f"(c3)
        : "r"(a0), "r"(a1), "r"(a2), "r"(a3), "r"(b0), "r"(b1));
}
static __device__ __forceinline__ void ldsm_x4(uint32_t& r0, uint32_t& r1,
                                               uint32_t& r2, uint32_t& r3,
                                               uint32_t saddr) {
    asm volatile("ldmatrix.sync.aligned.m8n8.x4.shared.b16 {%0,%1,%2,%3}, [%4];"
                 : "=r"(r0), "=r"(r1), "=r"(r2), "=r"(r3) : "r"(saddr));
}
static __device__ __forceinline__ void cp16(void* smem_dst, const void* gsrc) {
    uint32_t s = (uint32_t)__cvta_generic_to_shared(smem_dst);
    asm volatile("cp.async.ca.shared.global [%0], [%1], 16;"
                 :: "r"(s), "l"(gsrc) : "memory");
}
static __device__ __forceinline__ void cp_commit() {
    asm volatile("cp.async.commit_group;" ::: "memory");
}
static __device__ __forceinline__ void cp_wait0() {
    asm volatile("cp.async.wait_group 0;" ::: "memory");
}
static __device__ __forceinline__ void cp_wait1() {
    asm volatile("cp.async.wait_group 1;" ::: "memory");
}

// ---------------- graph preprocessing ----------------
__global__ void k_zero_deg(int n) {
    int i = blockIdx.x * blockDim.x + threadIdx.x;
    if (i < n) d_degi[i] = 0;
}
__global__ void k_degcnt(const int* __restrict__ dst, int e) {
    int i = blockIdx.x * blockDim.x + threadIdx.x;
    if (i < e) atomicAdd(&d_degi[dst[i]], 1);
}
__global__ void k_dinv(int n) {
    int i = blockIdx.x * blockDim.x + threadIdx.x;
    if (i < n) d_dinv[i] = rsqrtf((float)(d_degi[i] + 1));  // +1 self loop
}
__global__ void k_scanA(int n) {
    __shared__ int sm[SCAN_B];
    int b = blockIdx.x, t = threadIdx.x, gi = b * SCAN_B + t;
    int v = (gi < n) ? d_degi[gi] : 0;
    sm[t] = v; __syncthreads();
    #pragma unroll
    for (int s = 1; s < SCAN_B; s <<= 1) {
        int u = (t >= s) ? sm[t - s] : 0;
        __syncthreads(); sm[t] += u; __syncthreads();
    }
    if (gi < n) d_off[gi + 1] = sm[t];
    if (t == SCAN_B - 1) d_bsum[b] = sm[t];
}
__global__ void k_scanB(int nblk) {
    __shared__ int sm[MAXBLK];
    int t = threadIdx.x;
    int v = (t < nblk) ? d_bsum[t] : 0;
    sm[t] = v; __syncthreads();
    #pragma unroll
    for (int s = 1; s < MAXBLK; s <<= 1) {
        int u = (t >= s) ? sm[t - s] : 0;
        __syncthreads(); sm[t] += u; __syncthreads();
    }
    if (t < nblk) d_bsum2[t] = sm[t] - v;
    if (t == 0) d_off[0] = 0;
}
__global__ void k_scanC(int n) {
    int b = blockIdx.x, t = threadIdx.x, gi = b * SCAN_B + t;
    if (gi < n) {
        int o = d_off[gi + 1] + d_bsum2[b];
        d_off[gi + 1] = o;
        d_cur[gi] = o - d_degi[gi];
    }
}
__global__ void k_scatter(const int* __restrict__ src,
                          const int* __restrict__ dst, int e) {
    int i = blockIdx.x * blockDim.x + threadIdx.x;
    if (i < e) {
        int d = dst[i];
        int pos = atomicAdd(&d_cur[d], 1);
        d_csr[pos] = src[i];
    }
}
__global__ void k_build_wcat(const float* __restrict__ Wmu,
                             const float* __restrict__ Wlv) {
    int i = blockIdx.x * blockDim.x + threadIdx.x;
    if (i < HID * HID) {
        int k = i / HID, c = i % HID;
        d_Wcat[i] = (c < OUTC) ? Wmu[k * OUTC + c] : Wlv[k * OUTC + (c - OUTC)];
    }
}

// -------- tf32 tensor-core GEMM: C[M,128] = A[M,K] @ B[K,128] [*dinv] --------
// 256 thr = 8 warps (2M x 4N), warp tile 64x32, BK=32, 3-stage cp.async
// pipeline (2 tiles in flight). ldmatrix A fragments; cvt.rna on fragments.
template <int K>
__global__ void __launch_bounds__(256)
k_gemm(const float* __restrict__ A, const float* __restrict__ B,
       float* __restrict__ C, const float* __restrict__ dinv, int M) {
    constexpr int BM = 128, BN = 128, BK = 32;
    constexpr int NIT = K / BK;
    constexpr int ASTR = 36, BSTR = 136;
    constexpr int STG = 3;
    constexpr int ASZ = BM * ASTR;              // uint32 per A stage
    constexpr int BSZ = BK * BSTR;              // uint32 per B stage
    extern __shared__ uint32_t dyn[];
    uint32_t* sA = dyn;                         // STG x ASZ
    uint32_t* sB = dyn + STG * ASZ;             // STG x BSZ

    const int tid  = threadIdx.x;
    const int lane = tid & 31;
    const int wid  = tid >> 5;
    const int wm   = wid & 1;
    const int wn   = wid >> 1;
    const int gid  = lane >> 2;
    const int tq   = lane & 3;
    const int row0 = blockIdx.x * BM;

    const int lm_row  = lane & 15;
    const int lm_col4 = (lane >> 4) * 4;

    auto cpAB = [&](int it, int b) {
        int k0 = it * BK;
        #pragma unroll
        for (int i = 0; i < 4; i++) {           // A: 128 x 32 fp32
            int idx = tid + i * 256;
            int r = idx >> 3, c0 = (idx & 7) * 4;
            int gr = row0 + r;
            uint32_t* dst = &sA[b * ASZ + r * ASTR + c0];
            if (gr < M)
                cp16(dst, A + (size_t)gr * K + k0 + c0);
            else
                *(uint4*)dst = make_uint4(0, 0, 0, 0);
        }
        #pragma unroll
        for (int i = 0; i < 4; i++) {           // B: 32 x 128 fp32
            int idx = tid + i * 256;
            int r = idx >> 5, c0 = (idx & 31) * 4;
            cp16(&sB[b * BSZ + r * BSTR + c0],
                 B + (size_t)(it * BK + r) * BN + c0);
        }
        cp_commit();
    };

    float acc[4][4][4] = {};

    cpAB(0, 0);
    if (NIT > 1) cpAB(1, 1);

    int buf = 0;
    for (int it = 0; it < NIT; it++) {
        if (it + 1 < NIT) cp_wait1(); else cp_wait0();   // stage it landed
        __syncthreads();                                 // all done with it-1
        if (it + 2 < NIT) cpAB(it + 2, (buf + 2) % STG); // prefetch 2 ahead

        const uint32_t* pa = &sA[buf * ASZ];
        const uint32_t* pb = &sB[buf * BSZ];
        uint32_t abase[4];
        #pragma unroll
        for (int mt = 0; mt < 4; mt++) {
            int m = wm * 64 + mt * 16 + lm_row;
            abase[mt] = (uint32_t)__cvta_generic_to_shared(
                            &pa[m * ASTR + lm_col4]);
        }
        #pragma unroll
        for (int ks = 0; ks < 4; ks++) {
            const int kk = ks * 8;
            uint32_t af[4][4], bf[4][2];
            #pragma unroll
            for (int mt = 0; mt < 4; mt++) {
                uint32_t r0, r1, r2, r3;
                ldsm_x4(r0, r1, r2, r3, abase[mt] + kk * 4);
                af[mt][0] = bits2tf32(r0);
                af[mt][1] = bits2tf32(r1);
                af[mt][2] = bits2tf32(r2);
                af[mt][3] = bits2tf32(r3);
            }
            #pragma unroll
            for (int nt = 0; nt < 4; nt++) {
                int nn = wn * 32 + nt * 8 + gid;
                bf[nt][0] = bits2tf32(pb[(kk + tq    ) * BSTR + nn]);
                bf[nt][1] = bits2tf32(pb[(kk + tq + 4) * BSTR + nn]);
            }
            #pragma unroll
            for (int mt = 0; mt < 4; mt++)
                #pragma unroll
                for (int nt = 0; nt < 4; nt++)
                    mma_tf32_16x8x8(acc[mt][nt][0], acc[mt][nt][1],
                                    acc[mt][nt][2], acc[mt][nt][3],
                                    af[mt][0], af[mt][1], af[mt][2], af[mt][3],
                                    bf[nt][0], bf[nt][1]);
        }
        buf = (buf + 1) % STG;
    }

    #pragma unroll
    for (int mt = 0; mt < 4; mt++) {
        int ra = row0 + wm * 64 + mt * 16 + gid;
        int rb = ra + 8;
        #pragma unroll
        for (int nt = 0; nt < 4; nt++) {
            int col = wn * 32 + nt * 8 + 2 * tq;
            if (ra < M) {
                float s = dinv ? dinv[ra] : 1.0f;
                *(float2*)(C + (size_t)ra * BN + col) =
                    make_float2(acc[mt][nt][0] * s, acc[mt][nt][1] * s);
            }
            if (rb < M) {
                float s = dinv ? dinv[rb] : 1.0f;
                *(float2*)(C + (size_t)rb * BN + col) =
                    make_float2(acc[mt][nt][2] * s, acc[mt][nt][3] * s);
            }
        }
    }
}

#define GEMM_SMEM ((3 * 128 * 36 + 3 * 32 * 136) * 4)   // 107520 B

// -------- agg1: warp per node, MLP-4 gather; Hs unscaled --------
__global__ void k_agg1(const float* __restrict__ b1, int n) {
    int d = (blockIdx.x * blockDim.x + threadIdx.x) >> 5;
    int lane = threadIdx.x & 31;
    if (d >= n) return;
    const float4* base = (const float4*)d_Hs;
    float sd = d_dinv[d];
    float4 acc = base[(size_t)d * 32 + lane];           // self
    acc.x *= sd; acc.y *= sd; acc.z *= sd; acc.w *= sd;
    int beg = d_off[d], end = d_off[d + 1];
    for (int k = beg; k < end; k += 32) {
        int rem = end - k; if (rem > 32) rem = 32;
        int   s  = (lane < rem) ? d_csr[k + lane] : 0;
        float sv = (lane < rem) ? d_dinv[s] : 0.f;
        int j = 0;
        for (; j + 4 <= rem; j += 4) {
            int s0 = __shfl_sync(0xffffffffu, s, j);
            int s1 = __shfl_sync(0xffffffffu, s, j + 1);
            int s2 = __shfl_sync(0xffffffffu, s, j + 2);
            int s3 = __shfl_sync(0xffffffffu, s, j + 3);
            float d0 = __shfl_sync(0xffffffffu, sv, j);
            float d1 = __shfl_sync(0xffffffffu, sv, j + 1);
            float d2 = __shfl_sync(0xffffffffu, sv, j + 2);
            float d3 = __shfl_sync(0xffffffffu, sv, j + 3);
            float4 v0 = base[(size_t)s0 * 32 + lane];
            float4 v1 = base[(size_t)s1 * 32 + lane];
            float4 v2 = base[(size_t)s2 * 32 + lane];
            float4 v3 = base[(size_t)s3 * 32 + lane];
            acc.x += v0.x * d0 + v1.x * d1 + v2.x * d2 + v3.x * d3;
            acc.y += v0.y * d0 + v1.y * d1 + v2.y * d2 + v3.y * d3;
            acc.z += v0.z * d0 + v1.z * d1 + v2.z * d2 + v3.z * d3;
            acc.w += v0.w * d0 + v1.w * d1 + v2.w * d2 + v3.w * d3;
        }
        for (; j < rem; j++) {
            int   sj = __shfl_sync(0xffffffffu, s,  j);
            float dv = __shfl_sync(0xffffffffu, sv, j);
            float4 v = base[(size_t)sj * 32 + lane];
            acc.x += v.x * dv; acc.y += v.y * dv;
            acc.z += v.z * dv; acc.w += v.w * dv;
        }
    }
    float4 bb = *(const float4*)(b1 + lane * 4);
    float4 r;
    r.x = acc.x * sd + bb.x; r.y = acc.y * sd + bb.y;
    r.z = acc.z * sd + bb.z; r.w = acc.w * sd + bb.w;
    r.x = r.x >= 0.f ? r.x : 0.01f * r.x;
    r.y = r.y >= 0.f ? r.y : 0.01f * r.y;
    r.z = r.z >= 0.f ? r.z : 0.01f * r.z;
    r.w = r.w >= 0.f ? r.w : 0.01f * r.w;
    *(float4*)(d_H1 + (size_t)d * HID + lane * 4) = r;
}

// -------- agg2: warp per node, MLP-4 gather, Gs pre-scaled --------
__global__ void k_agg2(const float* __restrict__ bmu,
                       const float* __restrict__ blv,
                       float* __restrict__ mu, float* __restrict__ lv, int n) {
    int d = (blockIdx.x * blockDim.x + threadIdx.x) >> 5;
    int lane = threadIdx.x & 31;
    if (d >= n) return;
    const float4* base = (const float4*)d_Gs;
    float4 acc = base[(size_t)d * 32 + lane];           // self (pre-scaled)
    int beg = d_off[d], end = d_off[d + 1];
    for (int k = beg; k < end; k += 32) {
        int rem = end - k; if (rem > 32) rem = 32;
        int s = (lane < rem) ? d_csr[k + lane] : 0;
        int j = 0;
        for (; j + 4 <= rem; j += 4) {
            int s0 = __shfl_sync(0xffffffffu, s, j);
            int s1 = __shfl_sync(0xffffffffu, s, j + 1);
            int s2 = __shfl_sync(0xffffffffu, s, j + 2);
            int s3 = __shfl_sync(0xffffffffu, s, j + 3);
            float4 v0 = base[(size_t)s0 * 32 + lane];
            float4 v1 = base[(size_t)s1 * 32 + lane];
            float4 v2 = base[(size_t)s2 * 32 + lane];
            float4 v3 = base[(size_t)s3 * 32 + lane];
            acc.x += v0.x + v1.x + v2.x + v3.x;
            acc.y += v0.y + v1.y + v2.y + v3.y;
            acc.z += v0.z + v1.z + v2.z + v3.z;
            acc.w += v0.w + v1.w + v2.w + v3.w;
        }
        for (; j < rem; j++) {
            int sj = __shfl_sync(0xffffffffu, s, j);
            float4 v = base[(size_t)sj * 32 + lane];
            acc.x += v.x; acc.y += v.y; acc.z += v.z; acc.w += v.w;
        }
    }
    float sc = d_dinv[d];
    float4 bb = (lane < 16) ? *(const float4*)(bmu + lane * 4)
                            : *(const float4*)(blv + (lane - 16) * 4);
    float4 r;
    r.x = acc.x * sc + bb.x; r.y = acc.y * sc + bb.y;
    r.z = acc.z * sc + bb.z; r.w = acc.w * sc + bb.w;
    float* p = (lane < 16) ? (mu + (size_t)d * OUTC + lane * 4)
                           : (lv + (size_t)d * OUTC + (lane - 16) * 4);
    *(float4*)p = r;
}

// ---------------- launch ----------------
extern "C" void kernel_launch(void* const* d_in, const int* in_sizes, int n_in,
                              void* d_out, int out_size) {
    const float* x   = (const float*)d_in[0];
    const int*   ei  = (const int*)d_in[1];     // int32 (JAX x64 disabled)
    const float* W1  = (const float*)d_in[2];
    const float* b1  = (const float*)d_in[3];
    const float* Wmu = (const float*)d_in[4];
    const float* bmu = (const float*)d_in[5];
    const float* Wlv = (const float*)d_in[6];
    const float* blv = (const float*)d_in[7];

    const int e = in_sizes[1] / 2;
    const int n = in_sizes[0] / INC;
    const int* src = ei;
    const int* dst = ei + e;

    float* mu = (float*)d_out;
    float* lv = mu + (size_t)n * OUTC;

    float *hs_p, *h1_p, *gs_p, *wcat_p, *dinv_p;
    cudaGetSymbolAddress((void**)&hs_p,   d_Hs);
    cudaGetSymbolAddress((void**)&h1_p,   d_H1);
    cudaGetSymbolAddress((void**)&gs_p,   d_Gs);
    cudaGetSymbolAddress((void**)&wcat_p, d_Wcat);
    cudaGetSymbolAddress((void**)&dinv_p, d_dinv);

    static cudaStream_t s1 = nullptr;
    static cudaEvent_t  evFork = nullptr, evJoin = nullptr;
    if (!s1) {
        cudaStreamCreateWithFlags(&s1, cudaStreamNonBlocking);
        cudaEventCreateWithFlags(&evFork, cudaEventDisableTiming);
        cudaEventCreateWithFlags(&evJoin, cudaEventDisableTiming);
        cudaFuncSetAttribute(k_gemm<INC>,
            cudaFuncAttributeMaxDynamicSharedMemorySize, GEMM_SMEM);
        cudaFuncSetAttribute(k_gemm<HID>,
            cudaFuncAttributeMaxDynamicSharedMemorySize, GEMM_SMEM);
    }

    const int T = 256;
    const int nblk = (n + SCAN_B - 1) / SCAN_B;
    const int gblk = (n + 127) / 128;

    // fork: graph prep on s1 concurrent with GEMM1 on main stream.
    // GEMM1 stays at launch slot 4 so ncu captures it.
    cudaEventRecord(evFork, 0);
    cudaStreamWaitEvent(s1, evFork, 0);

    k_zero_deg<<<(n + T - 1) / T, T, 0, s1>>>(n);
    k_degcnt<<<(e + T - 1) / T, T, 0, s1>>>(dst, e);
    k_dinv<<<(n + T - 1) / T, T, 0, s1>>>(n);

    // GEMM1 (tf32 tensor cores, unscaled) — 4th launch (profiled)
    k_gemm<INC><<<gblk, 256, GEMM_SMEM>>>(x, W1, hs_p, nullptr, n);

    k_scanA<<<nblk, SCAN_B, 0, s1>>>(n);
    k_scanB<<<1, MAXBLK, 0, s1>>>(nblk);
    k_scanC<<<nblk, SCAN_B, 0, s1>>>(n);
    k_scatter<<<(e + T - 1) / T, T, 0, s1>>>(src, dst, e);
    k_build_wcat<<<(HID * HID + T - 1) / T, T, 0, s1>>>(Wmu, Wlv);

    // join
    cudaEventRecord(evJoin, s1);
    cudaStreamWaitEvent(0, evJoin, 0);

    // agg1 (folds all dinv scaling), GEMM2 (tf32), agg2
    k_agg1<<<(n * 32 + T - 1) / T, T>>>(b1, n);
    k_gemm<HID><<<gblk, 256, GEMM_SMEM>>>(h1_p, wcat_p, gs_p, dinv_p, n);
    k_agg2<<<(n * 32 + T - 1) / T, T>>>(bmu, blv, mu, lv, n);
}

// round 15
// speedup vs baseline: 1.0088x; 1.0088x over previous
#include <cuda_runtime.h>
#include <cstdint>

#define NN   100000
#define EE   1600000
#define INC  256
#define HID  128
#define OUTC 64
#define SCAN_B 128
#define MAXBLK 1024

// -------- scratch (__device__ globals; allocation is forbidden) --------
static __device__ __align__(256) int   d_degi[NN];
static __device__ __align__(256) int   d_off [NN + 1];
static __device__ __align__(256) int   d_cur [NN];
static __device__ __align__(256) int   d_csr [EE];
static __device__ __align__(256) int   d_bsum [MAXBLK];
static __device__ __align__(256) int   d_bsum2[MAXBLK];
static __device__ __align__(256) float d_dinv[NN];
static __device__ __align__(256) float d_Hs [(size_t)NN * HID];  // x@W1 (unscaled)
static __device__ __align__(256) float d_H1 [(size_t)NN * HID];  // leaky(agg1)
static __device__ __align__(256) float d_Gs [(size_t)NN * HID];  // dinv*(H1@Wcat)
static __device__ __align__(256) float d_Wcat[HID * HID];

// ---------------- tf32 / async helpers ----------------
static __device__ __forceinline__ uint32_t bits2tf32(uint32_t b) {
    uint32_t r;
    asm("cvt.rna.tf32.f32 %0, %1;" : "=r"(r) : "f"(__uint_as_float(b)));
    return r;
}
static __device__ __forceinline__ void mma_tf32_16x8x8(
    float& c0, float& c1, float& c2, float& c3,
    uint32_t a0, uint32_t a1, uint32_t a2, uint32_t a3,
    uint32_t b0, uint32_t b1) {
    asm volatile(
        "mma.sync.aligned.m16n8k8.row.col.f32.tf32.tf32.f32 "
        "{%0,%1,%2,%3}, {%4,%5,%6,%7}, {%8,%9}, {%0,%1,%2,%3};"
        : "+f"(c0), "+f"(c1), "+f"(c2), "+f"(c3)
        : "r"(a0), "r"(a1), "r"(a2), "r"(a3), "r"(b0), "r"(b1));
}
static __device__ __forceinline__ void ldsm_x4(uint32_t& r0, uint32_t& r1,
                                               uint32_t& r2, uint32_t& r3,
                                               uint32_t saddr) {
    asm volatile("ldmatrix.sync.aligned.m8n8.x4.shared.b16 {%0,%1,%2,%3}, [%4];"
                 : "=r"(r0), "=r"(r1), "=r"(r2), "=r"(r3) : "r"(saddr));
}
static __device__ __forceinline__ void cp16(void* smem_dst, const void* gsrc) {
    uint32_t s = (uint32_t)__cvta_generic_to_shared(smem_dst);
    asm volatile("cp.async.ca.shared.global [%0], [%1], 16;"
                 :: "r"(s), "l"(gsrc) : "memory");
}
static __device__ __forceinline__ void cp_commit() {
    asm volatile("cp.async.commit_group;" ::: "memory");
}
static __device__ __forceinline__ void cp_wait0() {
    asm volatile("cp.async.wait_group 0;" ::: "memory");
}

// ---------------- graph preprocessing ----------------
__global__ void k_zero_deg(int n) {
    int i = blockIdx.x * blockDim.x + threadIdx.x;
    if (i < n) d_degi[i] = 0;
}
__global__ void k_degcnt(const int* __restrict__ dst, int e) {
    int i = blockIdx.x * blockDim.x + threadIdx.x;
    if (i < e) atomicAdd(&d_degi[dst[i]], 1);
}
__global__ void k_dinv(int n) {
    int i = blockIdx.x * blockDim.x + threadIdx.x;
    if (i < n) d_dinv[i] = rsqrtf((float)(d_degi[i] + 1));  // +1 self loop
}
__global__ void k_scanA(int n) {
    __shared__ int sm[SCAN_B];
    int b = blockIdx.x, t = threadIdx.x, gi = b * SCAN_B + t;
    int v = (gi < n) ? d_degi[gi] : 0;
    sm[t] = v; __syncthreads();
    #pragma unroll
    for (int s = 1; s < SCAN_B; s <<= 1) {
        int u = (t >= s) ? sm[t - s] : 0;
        __syncthreads(); sm[t] += u; __syncthreads();
    }
    if (gi < n) d_off[gi + 1] = sm[t];
    if (t == SCAN_B - 1) d_bsum[b] = sm[t];
}
__global__ void k_scanB(int nblk) {
    __shared__ int sm[MAXBLK];
    int t = threadIdx.x;
    int v = (t < nblk) ? d_bsum[t] : 0;
    sm[t] = v; __syncthreads();
    #pragma unroll
    for (int s = 1; s < MAXBLK; s <<= 1) {
        int u = (t >= s) ? sm[t - s] : 0;
        __syncthreads(); sm[t] += u; __syncthreads();
    }
    if (t < nblk) d_bsum2[t] = sm[t] - v;
    if (t == 0) d_off[0] = 0;
}
__global__ void k_scanC(int n) {
    int b = blockIdx.x, t = threadIdx.x, gi = b * SCAN_B + t;
    if (gi < n) {
        int o = d_off[gi + 1] + d_bsum2[b];
        d_off[gi + 1] = o;
        d_cur[gi] = o - d_degi[gi];
    }
}
__global__ void k_scatter(const int* __restrict__ src,
                          const int* __restrict__ dst, int e) {
    int i = blockIdx.x * blockDim.x + threadIdx.x;
    if (i < e) {
        int d = dst[i];
        int pos = atomicAdd(&d_cur[d], 1);
        d_csr[pos] = src[i];
    }
}
__global__ void k_build_wcat(const float* __restrict__ Wmu,
                             const float* __restrict__ Wlv) {
    int i = blockIdx.x * blockDim.x + threadIdx.x;
    if (i < HID * HID) {
        int k = i / HID, c = i % HID;
        d_Wcat[i] = (c < OUTC) ? Wmu[k * OUTC + c] : Wlv[k * OUTC + (c - OUTC)];
    }
}

// -------- tf32 tensor-core GEMM: C[M,128] = A[M,K] @ B[K,128] [*dinv] --------
// BM=64, BN=128, BK=32. 256 thr = 8 warps (2M x 4N), warp tile 32x32.
// 4 CTAs/SM target (launch_bounds 256,4). 2-stage cp.async; ldmatrix A frags.
template <int K>
__global__ void __launch_bounds__(256, 4)
k_gemm(const float* __restrict__ A, const float* __restrict__ B,
       float* __restrict__ C, const float* __restrict__ dinv, int M) {
    constexpr int BM = 64, BN = 128, BK = 32;
    constexpr int NIT = K / BK;
    constexpr int ASTR = 36, BSTR = 136;
    constexpr int ASZ = BM * ASTR;
    constexpr int BSZ = BK * BSTR;
    extern __shared__ uint32_t dyn[];
    uint32_t* sA = dyn;                         // 2 x 64 x 36
    uint32_t* sB = dyn + 2 * ASZ;               // 2 x 32 x 136

    const int tid  = threadIdx.x;
    const int lane = tid & 31;
    const int wid  = tid >> 5;
    const int wm   = wid & 1;          // 0..1 -> M offset wm*32
    const int wn   = wid >> 1;         // 0..3 -> N offset wn*32
    const int gid  = lane >> 2;
    const int tq   = lane & 3;
    const int row0 = blockIdx.x * BM;

    const int lm_row  = lane & 15;
    const int lm_col4 = (lane >> 4) * 4;

    auto cpAB = [&](int it, int b) {
        int k0 = it * BK;
        #pragma unroll
        for (int i = 0; i < 2; i++) {           // A: 64 x 32 fp32 = 512 float4
            int idx = tid + i * 256;
            int r = idx >> 3, c0 = (idx & 7) * 4;
            int gr = row0 + r;
            uint32_t* dst = &sA[b * ASZ + r * ASTR + c0];
            if (gr < M)
                cp16(dst, A + (size_t)gr * K + k0 + c0);
            else
                *(uint4*)dst = make_uint4(0, 0, 0, 0);
        }
        #pragma unroll
        for (int i = 0; i < 4; i++) {           // B: 32 x 128 fp32
            int idx = tid + i * 256;
            int r = idx >> 5, c0 = (idx & 31) * 4;
            cp16(&sB[b * BSZ + r * BSTR + c0],
                 B + (size_t)(it * BK + r) * BN + c0);
        }
        cp_commit();
    };

    float acc[2][4][4] = {};

    cpAB(0, 0);
    cp_wait0();
    __syncthreads();

    int buf = 0;
    for (int it = 0; it < NIT; it++) {
        if (it + 1 < NIT) cpAB(it + 1, buf ^ 1);   // async fill during MMA
        const uint32_t* pa = &sA[buf * ASZ];
        const uint32_t* pb = &sB[buf * BSZ];
        uint32_t abase[2];
        #pragma unroll
        for (int mt = 0; mt < 2; mt++) {
            int m = wm * 32 + mt * 16 + lm_row;
            abase[mt] = (uint32_t)__cvta_generic_to_shared(
                            &pa[m * ASTR + lm_col4]);
        }
        #pragma unroll
        for (int ks = 0; ks < 4; ks++) {
            const int kk = ks * 8;
            uint32_t af[2][4], bf[4][2];
            #pragma unroll
            for (int mt = 0; mt < 2; mt++) {
                uint32_t r0, r1, r2, r3;
                ldsm_x4(r0, r1, r2, r3, abase[mt] + kk * 4);
                af[mt][0] = bits2tf32(r0);
                af[mt][1] = bits2tf32(r1);
                af[mt][2] = bits2tf32(r2);
                af[mt][3] = bits2tf32(r3);
            }
            #pragma unroll
            for (int nt = 0; nt < 4; nt++) {
                int nn = wn * 32 + nt * 8 + gid;
                bf[nt][0] = bits2tf32(pb[(kk + tq    ) * BSTR + nn]);
                bf[nt][1] = bits2tf32(pb[(kk + tq + 4) * BSTR + nn]);
            }
            #pragma unroll
            for (int mt = 0; mt < 2; mt++)
                #pragma unroll
                for (int nt = 0; nt < 4; nt++)
                    mma_tf32_16x8x8(acc[mt][nt][0], acc[mt][nt][1],
                                    acc[mt][nt][2], acc[mt][nt][3],
                                    af[mt][0], af[mt][1], af[mt][2], af[mt][3],
                                    bf[nt][0], bf[nt][1]);
        }
        if (it + 1 < NIT) cp_wait0();
        __syncthreads();
        buf ^= 1;
    }

    #pragma unroll
    for (int mt = 0; mt < 2; mt++) {
        int ra = row0 + wm * 32 + mt * 16 + gid;
        int rb = ra + 8;
        #pragma unroll
        for (int nt = 0; nt < 4; nt++) {
            int col = wn * 32 + nt * 8 + 2 * tq;
            if (ra < M) {
                float s = dinv ? dinv[ra] : 1.0f;
                *(float2*)(C + (size_t)ra * BN + col) =
                    make_float2(acc[mt][nt][0] * s, acc[mt][nt][1] * s);
            }
            if (rb < M) {
                float s = dinv ? dinv[rb] : 1.0f;
                *(float2*)(C + (size_t)rb * BN + col) =
                    make_float2(acc[mt][nt][2] * s, acc[mt][nt][3] * s);
            }
        }
    }
}

#define GEMM_SMEM ((2 * 64 * 36 + 2 * 32 * 136) * 4)   // 53248 B

// -------- agg1: warp per node, MLP-4 gather; Hs unscaled --------
__global__ void k_agg1(const float* __restrict__ b1, int n) {
    int d = (blockIdx.x * blockDim.x + threadIdx.x) >> 5;
    int lane = threadIdx.x & 31;
    if (d >= n) return;
    const float4* base = (const float4*)d_Hs;
    float sd = d_dinv[d];
    float4 acc = base[(size_t)d * 32 + lane];           // self
    acc.x *= sd; acc.y *= sd; acc.z *= sd; acc.w *= sd;
    int beg = d_off[d], end = d_off[d + 1];
    for (int k = beg; k < end; k += 32) {
        int rem = end - k; if (rem > 32) rem = 32;
        int   s  = (lane < rem) ? d_csr[k + lane] : 0;
        float sv = (lane < rem) ? d_dinv[s] : 0.f;
        int j = 0;
        for (; j + 4 <= rem; j += 4) {
            int s0 = __shfl_sync(0xffffffffu, s, j);
            int s1 = __shfl_sync(0xffffffffu, s, j + 1);
            int s2 = __shfl_sync(0xffffffffu, s, j + 2);
            int s3 = __shfl_sync(0xffffffffu, s, j + 3);
            float d0 = __shfl_sync(0xffffffffu, sv, j);
            float d1 = __shfl_sync(0xffffffffu, sv, j + 1);
            float d2 = __shfl_sync(0xffffffffu, sv, j + 2);
            float d3 = __shfl_sync(0xffffffffu, sv, j + 3);
            float4 v0 = base[(size_t)s0 * 32 + lane];
            float4 v1 = base[(size_t)s1 * 32 + lane];
            float4 v2 = base[(size_t)s2 * 32 + lane];
            float4 v3 = base[(size_t)s3 * 32 + lane];
            acc.x += v0.x * d0 + v1.x * d1 + v2.x * d2 + v3.x * d3;
            acc.y += v0.y * d0 + v1.y * d1 + v2.y * d2 + v3.y * d3;
            acc.z += v0.z * d0 + v1.z * d1 + v2.z * d2 + v3.z * d3;
            acc.w += v0.w * d0 + v1.w * d1 + v2.w * d2 + v3.w * d3;
        }
        for (; j < rem; j++) {
            int   sj = __shfl_sync(0xffffffffu, s,  j);
            float dv = __shfl_sync(0xffffffffu, sv, j);
            float4 v = base[(size_t)sj * 32 + lane];
            acc.x += v.x * dv; acc.y += v.y * dv;
            acc.z += v.z * dv; acc.w += v.w * dv;
        }
    }
    float4 bb = *(const float4*)(b1 + lane * 4);
    float4 r;
    r.x = acc.x * sd + bb.x; r.y = acc.y * sd + bb.y;
    r.z = acc.z * sd + bb.z; r.w = acc.w * sd + bb.w;
    r.x = r.x >= 0.f ? r.x : 0.01f * r.x;
    r.y = r.y >= 0.f ? r.y : 0.01f * r.y;
    r.z = r.z >= 0.f ? r.z : 0.01f * r.z;
    r.w = r.w >= 0.f ? r.w : 0.01f * r.w;
    *(float4*)(d_H1 + (size_t)d * HID + lane * 4) = r;
}

// -------- agg2: warp per node, MLP-4 gather, Gs pre-scaled --------
__global__ void k_agg2(const float* __restrict__ bmu,
                       const float* __restrict__ blv,
                       float* __restrict__ mu, float* __restrict__ lv, int n) {
    int d = (blockIdx.x * blockDim.x + threadIdx.x) >> 5;
    int lane = threadIdx.x & 31;
    if (d >= n) return;
    const float4* base = (const float4*)d_Gs;
    float4 acc = base[(size_t)d * 32 + lane];           // self (pre-scaled)
    int beg = d_off[d], end = d_off[d + 1];
    for (int k = beg; k < end; k += 32) {
        int rem = end - k; if (rem > 32) rem = 32;
        int s = (lane < rem) ? d_csr[k + lane] : 0;
        int j = 0;
        for (; j + 4 <= rem; j += 4) {
            int s0 = __shfl_sync(0xffffffffu, s, j);
            int s1 = __shfl_sync(0xffffffffu, s, j + 1);
            int s2 = __shfl_sync(0xffffffffu, s, j + 2);
            int s3 = __shfl_sync(0xffffffffu, s, j + 3);
            float4 v0 = base[(size_t)s0 * 32 + lane];
            float4 v1 = base[(size_t)s1 * 32 + lane];
            float4 v2 = base[(size_t)s2 * 32 + lane];
            float4 v3 = base[(size_t)s3 * 32 + lane];
            acc.x += v0.x + v1.x + v2.x + v3.x;
            acc.y += v0.y + v1.y + v2.y + v3.y;
            acc.z += v0.z + v1.z + v2.z + v3.z;
            acc.w += v0.w + v1.w + v2.w + v3.w;
        }
        for (; j < rem; j++) {
            int sj = __shfl_sync(0xffffffffu, s, j);
            float4 v = base[(size_t)sj * 32 + lane];
            acc.x += v.x; acc.y += v.y; acc.z += v.z; acc.w += v.w;
        }
    }
    float sc = d_dinv[d];
    float4 bb = (lane < 16) ? *(const float4*)(bmu + lane * 4)
                            : *(const float4*)(blv + (lane - 16) * 4);
    float4 r;
    r.x = acc.x * sc + bb.x; r.y = acc.y * sc + bb.y;
    r.z = acc.z * sc + bb.z; r.w = acc.w * sc + bb.w;
    float* p = (lane < 16) ? (mu + (size_t)d * OUTC + lane * 4)
                           : (lv + (size_t)d * OUTC + (lane - 16) * 4);
    *(float4*)p = r;
}

// ---------------- launch ----------------
extern "C" void kernel_launch(void* const* d_in, const int* in_sizes, int n_in,
                              void* d_out, int out_size) {
    const float* x   = (const float*)d_in[0];
    const int*   ei  = (const int*)d_in[1];     // int32 (JAX x64 disabled)
    const float* W1  = (const float*)d_in[2];
    const float* b1  = (const float*)d_in[3];
    const float* Wmu = (const float*)d_in[4];
    const float* bmu = (const float*)d_in[5];
    const float* Wlv = (const float*)d_in[6];
    const float* blv = (const float*)d_in[7];

    const int e = in_sizes[1] / 2;
    const int n = in_sizes[0] / INC;
    const int* src = ei;
    const int* dst = ei + e;

    float* mu = (float*)d_out;
    float* lv = mu + (size_t)n * OUTC;

    float *hs_p, *h1_p, *gs_p, *wcat_p, *dinv_p;
    cudaGetSymbolAddress((void**)&hs_p,   d_Hs);
    cudaGetSymbolAddress((void**)&h1_p,   d_H1);
    cudaGetSymbolAddress((void**)&gs_p,   d_Gs);
    cudaGetSymbolAddress((void**)&wcat_p, d_Wcat);
    cudaGetSymbolAddress((void**)&dinv_p, d_dinv);

    static cudaStream_t s1 = nullptr;
    static cudaEvent_t  evFork = nullptr, evJoin = nullptr;
    if (!s1) {
        cudaStreamCreateWithFlags(&s1, cudaStreamNonBlocking);
        cudaEventCreateWithFlags(&evFork, cudaEventDisableTiming);
        cudaEventCreateWithFlags(&evJoin, cudaEventDisableTiming);
        cudaFuncSetAttribute(k_gemm<INC>,
            cudaFuncAttributeMaxDynamicSharedMemorySize, GEMM_SMEM);
        cudaFuncSetAttribute(k_gemm<HID>,
            cudaFuncAttributeMaxDynamicSharedMemorySize, GEMM_SMEM);
    }

    const int T = 256;
    const int nblk = (n + SCAN_B - 1) / SCAN_B;
    const int gblk = (n + 63) / 64;              // BM=64 -> 1563 CTAs

    // fork: graph prep on s1 concurrent with GEMM1 on main stream.
    // GEMM1 stays at launch slot 4 so ncu captures it.
    cudaEventRecord(evFork, 0);
    cudaStreamWaitEvent(s1, evFork, 0);

    k_zero_deg<<<(n + T - 1) / T, T, 0, s1>>>(n);
    k_degcnt<<<(e + T - 1) / T, T, 0, s1>>>(dst, e);
    k_dinv<<<(n + T - 1) / T, T, 0, s1>>>(n);

    // GEMM1 (tf32 tensor cores, unscaled) — 4th launch (profiled)
    k_gemm<INC><<<gblk, 256, GEMM_SMEM>>>(x, W1, hs_p, nullptr, n);

    k_scanA<<<nblk, SCAN_B, 0, s1>>>(n);
    k_scanB<<<1, MAXBLK, 0, s1>>>(nblk);
    k_scanC<<<nblk, SCAN_B, 0, s1>>>(n);
    k_scatter<<<(e + T - 1) / T, T, 0, s1>>>(src, dst, e);
    k_build_wcat<<<(HID * HID + T - 1) / T, T, 0, s1>>>(Wmu, Wlv);

    // join
    cudaEventRecord(evJoin, s1);
    cudaStreamWaitEvent(0, evJoin, 0);

    // agg1 (folds all dinv scaling), GEMM2 (tf32), agg2
    k_agg1<<<(n * 32 + T - 1) / T, T>>>(b1, n);
    k_gemm<HID><<<gblk, 256, GEMM_SMEM>>>(h1_p, wcat_p, gs_p, dinv_p, n);
    k_agg2<<<(n * 32 + T - 1) / T, T>>>(bmu, blv, mu, lv, n);
}

// round 16
// speedup vs baseline: 1.1037x; 1.0940x over previous
#include <cuda_runtime.h>
#include <cstdint>

#define NN   100000
#define EE   1600000
#define INC  256
#define HID  128
#define OUTC 64
#define SCAN_B 128
#define MAXBLK 1024

// -------- scratch (__device__ globals; allocation is forbidden) --------
static __device__ __align__(256) int   d_degi[NN];
static __device__ __align__(256) int   d_off [NN + 1];
static __device__ __align__(256) int   d_cur [NN];
static __device__ __align__(256) int   d_csr [EE];
static __device__ __align__(256) int   d_bsum [MAXBLK];
static __device__ __align__(256) int   d_bsum2[MAXBLK];
static __device__ __align__(256) float d_dinv[NN];
static __device__ __align__(256) float d_Hs [(size_t)NN * HID];  // x@W1 (unscaled)
static __device__ __align__(256) float d_H1 [(size_t)NN * HID];  // leaky(agg1)
static __device__ __align__(256) float d_Gs [(size_t)NN * HID];  // dinv*(H1@Wcat)
static __device__ __align__(256) float d_W1c [INC * HID];        // W1 pre-cvt tf32
static __device__ __align__(256) float d_Wcat[HID * HID];        // [Wmu|Wlv] tf32

// ---------------- tf32 / async helpers ----------------
static __device__ __forceinline__ uint32_t f2tf32(float f) {
    uint32_t r;
    asm("cvt.rna.tf32.f32 %0, %1;" : "=r"(r) : "f"(f));
    return r;
}
static __device__ __forceinline__ void mma_tf32_16x8x8(
    float& c0, float& c1, float& c2, float& c3,
    uint32_t a0, uint32_t a1, uint32_t a2, uint32_t a3,
    uint32_t b0, uint32_t b1) {
    asm volatile(
        "mma.sync.aligned.m16n8k8.row.col.f32.tf32.tf32.f32 "
        "{%0,%1,%2,%3}, {%4,%5,%6,%7}, {%8,%9}, {%0,%1,%2,%3};"
        : "+f"(c0), "+f"(c1), "+f"(c2), "+f"(c3)
        : "r"(a0), "r"(a1), "r"(a2), "r"(a3), "r"(b0), "r"(b1));
}
static __device__ __forceinline__ void cp16(void* smem_dst, const void* gsrc) {
    uint32_t s = (uint32_t)__cvta_generic_to_shared(smem_dst);
    asm volatile("cp.async.ca.shared.global [%0], [%1], 16;"
                 :: "r"(s), "l"(gsrc) : "memory");
}
static __device__ __forceinline__ void cp_commit() {
    asm volatile("cp.async.commit_group;" ::: "memory");
}
static __device__ __forceinline__ void cp_wait0() {
    asm volatile("cp.async.wait_group 0;" ::: "memory");
}

// ---------------- graph preprocessing ----------------
__global__ void k_cvt_w1(const float* __restrict__ W1) {
    int i = blockIdx.x * blockDim.x + threadIdx.x;   // INC*HID = 32768
    if (i < INC * HID)
        ((uint32_t*)d_W1c)[i] = f2tf32(W1[i]);
}
__global__ void k_zero_deg(int n) {
    int i = blockIdx.x * blockDim.x + threadIdx.x;
    if (i < n) d_degi[i] = 0;
}
__global__ void k_degcnt(const int* __restrict__ dst, int e) {
    int i = blockIdx.x * blockDim.x + threadIdx.x;
    if (i < e) atomicAdd(&d_degi[dst[i]], 1);
}
__global__ void k_dinv(int n) {
    int i = blockIdx.x * blockDim.x + threadIdx.x;
    if (i < n) d_dinv[i] = rsqrtf((float)(d_degi[i] + 1));  // +1 self loop
}
__global__ void k_scanA(int n) {
    __shared__ int sm[SCAN_B];
    int b = blockIdx.x, t = threadIdx.x, gi = b * SCAN_B + t;
    int v = (gi < n) ? d_degi[gi] : 0;
    sm[t] = v; __syncthreads();
    #pragma unroll
    for (int s = 1; s < SCAN_B; s <<= 1) {
        int u = (t >= s) ? sm[t - s] : 0;
        __syncthreads(); sm[t] += u; __syncthreads();
    }
    if (gi < n) d_off[gi + 1] = sm[t];
    if (t == SCAN_B - 1) d_bsum[b] = sm[t];
}
__global__ void k_scanB(int nblk) {
    __shared__ int sm[MAXBLK];
    int t = threadIdx.x;
    int v = (t < nblk) ? d_bsum[t] : 0;
    sm[t] = v; __syncthreads();
    #pragma unroll
    for (int s = 1; s < MAXBLK; s <<= 1) {
        int u = (t >= s) ? sm[t - s] : 0;
        __syncthreads(); sm[t] += u; __syncthreads();
    }
    if (t < nblk) d_bsum2[t] = sm[t] - v;
    if (t == 0) d_off[0] = 0;
}
__global__ void k_scanC(int n) {
    int b = blockIdx.x, t = threadIdx.x, gi = b * SCAN_B + t;
    if (gi < n) {
        int o = d_off[gi + 1] + d_bsum2[b];
        d_off[gi + 1] = o;
        d_cur[gi] = o - d_degi[gi];
    }
}
__global__ void k_scatter(const int* __restrict__ src,
                          const int* __restrict__ dst, int e) {
    int i = blockIdx.x * blockDim.x + threadIdx.x;
    if (i < e) {
        int d = dst[i];
        int pos = atomicAdd(&d_cur[d], 1);
        d_csr[pos] = src[i];
    }
}
__global__ void k_build_wcat(const float* __restrict__ Wmu,
                             const float* __restrict__ Wlv) {
    int i = blockIdx.x * blockDim.x + threadIdx.x;
    if (i < HID * HID) {
        int k = i / HID, c = i % HID;
        float v = (c < OUTC) ? Wmu[k * OUTC + c] : Wlv[k * OUTC + (c - OUTC)];
        ((uint32_t*)d_Wcat)[i] = f2tf32(v);      // pre-converted tf32 bits
    }
}

// -------- tf32 tensor-core GEMM: C[M,128] = A[M,K] @ Btf32[K,128] [*dinv] --------
// 256 thr = 8 warps (2M x 4N), warp tile 64x32, BK=32, 2-stage.
// A: LDG->cvt->STS (reg staged). B: pre-converted tf32 bits via cp.async,
// fragments loaded with plain LDS (no cvt in the inner loop).
template <int K>
__global__ void __launch_bounds__(256)
k_gemm(const float* __restrict__ A, const float* __restrict__ B,
       float* __restrict__ C, const float* __restrict__ dinv, int M) {
    constexpr int BM = 128, BN = 128, BK = 32;
    constexpr int NIT = K / BK;
    constexpr int ASTR = 36, BSTR = 136;
    extern __shared__ uint32_t dyn[];
    uint32_t* sA = dyn;                         // 2 x 128 x 36
    uint32_t* sB = dyn + 2 * BM * ASTR;         // 2 x 32 x 136

    const int tid  = threadIdx.x;
    const int lane = tid & 31;
    const int wid  = tid >> 5;
    const int wm   = wid & 1;
    const int wn   = wid >> 1;
    const int gid  = lane >> 2;
    const int tq   = lane & 3;
    const int row0 = blockIdx.x * BM;

    float4 av[4];
    auto gloadA = [&](int it) {
        int k0 = it * BK;
        #pragma unroll
        for (int i = 0; i < 4; i++) {
            int idx = tid + i * 256;
            int r = idx >> 3, c0 = (idx & 7) * 4;
            int gr = row0 + r;
            av[i] = (gr < M)
                ? *(const float4*)(A + (size_t)gr * K + k0 + c0)
                : make_float4(0.f, 0.f, 0.f, 0.f);
        }
    };
    auto stsA = [&](int b) {
        #pragma unroll
        for (int i = 0; i < 4; i++) {
            int idx = tid + i * 256;
            int r = idx >> 3, c0 = (idx & 7) * 4;
            uint4 t = make_uint4(f2tf32(av[i].x), f2tf32(av[i].y),
                                 f2tf32(av[i].z), f2tf32(av[i].w));
            *(uint4*)&sA[b * BM * ASTR + r * ASTR + c0] = t;
        }
    };
    auto cpB = [&](int it, int b) {
        #pragma unroll
        for (int i = 0; i < 4; i++) {
            int idx = tid + i * 256;
            int r = idx >> 5, c0 = (idx & 31) * 4;
            cp16(&sB[b * BK * BSTR + r * BSTR + c0],
                 B + (size_t)(it * BK + r) * BN + c0);
        }
        cp_commit();
    };

    float acc[4][4][4] = {};

    gloadA(0);
    cpB(0, 0);
    stsA(0);
    cp_wait0();
    __syncthreads();

    int buf = 0;
    for (int it = 0; it < NIT; it++) {
        if (it + 1 < NIT) {
            gloadA(it + 1);            // LDG in flight during MMA
            cpB(it + 1, buf ^ 1);      // cp.async in flight during MMA
        }
        const uint32_t* pa = &sA[buf * BM * ASTR];
        const uint32_t* pb = &sB[buf * BK * BSTR];
        #pragma unroll
        for (int ks = 0; ks < 4; ks++) {
            const int kk = ks * 8;
            uint32_t af[4][4], bf[4][2];
            #pragma unroll
            for (int mt = 0; mt < 4; mt++) {
                int m = wm * 64 + mt * 16 + gid;
                af[mt][0] = pa[(m    ) * ASTR + kk + tq];
                af[mt][1] = pa[(m + 8) * ASTR + kk + tq];
                af[mt][2] = pa[(m    ) * ASTR + kk + tq + 4];
                af[mt][3] = pa[(m + 8) * ASTR + kk + tq + 4];
            }
            #pragma unroll
            for (int nt = 0; nt < 4; nt++) {
                int nn = wn * 32 + nt * 8 + gid;
                bf[nt][0] = pb[(kk + tq    ) * BSTR + nn];   // already tf32
                bf[nt][1] = pb[(kk + tq + 4) * BSTR + nn];
            }
            #pragma unroll
            for (int mt = 0; mt < 4; mt++)
                #pragma unroll
                for (int nt = 0; nt < 4; nt++)
                    mma_tf32_16x8x8(acc[mt][nt][0], acc[mt][nt][1],
                                    acc[mt][nt][2], acc[mt][nt][3],
                                    af[mt][0], af[mt][1], af[mt][2], af[mt][3],
                                    bf[nt][0], bf[nt][1]);
        }
        if (it + 1 < NIT) {
            stsA(buf ^ 1);
            cp_wait0();
        }
        __syncthreads();
        buf ^= 1;
    }

    #pragma unroll
    for (int mt = 0; mt < 4; mt++) {
        int ra = row0 + wm * 64 + mt * 16 + gid;
        int rb = ra + 8;
        #pragma unroll
        for (int nt = 0; nt < 4; nt++) {
            int col = wn * 32 + nt * 8 + 2 * tq;
            if (ra < M) {
                float s = dinv ? dinv[ra] : 1.0f;
                *(float2*)(C + (size_t)ra * BN + col) =
                    make_float2(acc[mt][nt][0] * s, acc[mt][nt][1] * s);
            }
            if (rb < M) {
                float s = dinv ? dinv[rb] : 1.0f;
                *(float2*)(C + (size_t)rb * BN + col) =
                    make_float2(acc[mt][nt][2] * s, acc[mt][nt][3] * s);
            }
        }
    }
}

#define GEMM_SMEM ((2 * 128 * 36 + 2 * 32 * 136) * 4)   // 71680 B

// -------- agg1: warp per node, MLP-4 gather; Hs unscaled --------
__global__ void k_agg1(const float* __restrict__ b1, int n) {
    int d = (blockIdx.x * blockDim.x + threadIdx.x) >> 5;
    int lane = threadIdx.x & 31;
    if (d >= n) return;
    const float4* base = (const float4*)d_Hs;
    float sd = d_dinv[d];
    float4 acc = base[(size_t)d * 32 + lane];           // self
    acc.x *= sd; acc.y *= sd; acc.z *= sd; acc.w *= sd;
    int beg = d_off[d], end = d_off[d + 1];
    for (int k = beg; k < end; k += 32) {
        int rem = end - k; if (rem > 32) rem = 32;
        int   s  = (lane < rem) ? d_csr[k + lane] : 0;
        float sv = (lane < rem) ? d_dinv[s] : 0.f;
        int j = 0;
        for (; j + 4 <= rem; j += 4) {
            int s0 = __shfl_sync(0xffffffffu, s, j);
            int s1 = __shfl_sync(0xffffffffu, s, j + 1);
            int s2 = __shfl_sync(0xffffffffu, s, j + 2);
            int s3 = __shfl_sync(0xffffffffu, s, j + 3);
            float d0 = __shfl_sync(0xffffffffu, sv, j);
            float d1 = __shfl_sync(0xffffffffu, sv, j + 1);
            float d2 = __shfl_sync(0xffffffffu, sv, j + 2);
            float d3 = __shfl_sync(0xffffffffu, sv, j + 3);
            float4 v0 = base[(size_t)s0 * 32 + lane];
            float4 v1 = base[(size_t)s1 * 32 + lane];
            float4 v2 = base[(size_t)s2 * 32 + lane];
            float4 v3 = base[(size_t)s3 * 32 + lane];
            acc.x += v0.x * d0 + v1.x * d1 + v2.x * d2 + v3.x * d3;
            acc.y += v0.y * d0 + v1.y * d1 + v2.y * d2 + v3.y * d3;
            acc.z += v0.z * d0 + v1.z * d1 + v2.z * d2 + v3.z * d3;
            acc.w += v0.w * d0 + v1.w * d1 + v2.w * d2 + v3.w * d3;
        }
        for (; j < rem; j++) {
            int   sj = __shfl_sync(0xffffffffu, s,  j);
            float dv = __shfl_sync(0xffffffffu, sv, j);
            float4 v = base[(size_t)sj * 32 + lane];
            acc.x += v.x * dv; acc.y += v.y * dv;
            acc.z += v.z * dv; acc.w += v.w * dv;
        }
    }
    float4 bb = *(const float4*)(b1 + lane * 4);
    float4 r;
    r.x = acc.x * sd + bb.x; r.y = acc.y * sd + bb.y;
    r.z = acc.z * sd + bb.z; r.w = acc.w * sd + bb.w;
    r.x = r.x >= 0.f ? r.x : 0.01f * r.x;
    r.y = r.y >= 0.f ? r.y : 0.01f * r.y;
    r.z = r.z >= 0.f ? r.z : 0.01f * r.z;
    r.w = r.w >= 0.f ? r.w : 0.01f * r.w;
    *(float4*)(d_H1 + (size_t)d * HID + lane * 4) = r;
}

// -------- agg2: warp per node, MLP-4 gather, Gs pre-scaled --------
__global__ void k_agg2(const float* __restrict__ bmu,
                       const float* __restrict__ blv,
                       float* __restrict__ mu, float* __restrict__ lv, int n) {
    int d = (blockIdx.x * blockDim.x + threadIdx.x) >> 5;
    int lane = threadIdx.x & 31;
    if (d >= n) return;
    const float4* base = (const float4*)d_Gs;
    float4 acc = base[(size_t)d * 32 + lane];           // self (pre-scaled)
    int beg = d_off[d], end = d_off[d + 1];
    for (int k = beg; k < end; k += 32) {
        int rem = end - k; if (rem > 32) rem = 32;
        int s = (lane < rem) ? d_csr[k + lane] : 0;
        int j = 0;
        for (; j + 4 <= rem; j += 4) {
            int s0 = __shfl_sync(0xffffffffu, s, j);
            int s1 = __shfl_sync(0xffffffffu, s, j + 1);
            int s2 = __shfl_sync(0xffffffffu, s, j + 2);
            int s3 = __shfl_sync(0xffffffffu, s, j + 3);
            float4 v0 = base[(size_t)s0 * 32 + lane];
            float4 v1 = base[(size_t)s1 * 32 + lane];
            float4 v2 = base[(size_t)s2 * 32 + lane];
            float4 v3 = base[(size_t)s3 * 32 + lane];
            acc.x += v0.x + v1.x + v2.x + v3.x;
            acc.y += v0.y + v1.y + v2.y + v3.y;
            acc.z += v0.z + v1.z + v2.z + v3.z;
            acc.w += v0.w + v1.w + v2.w + v3.w;
        }
        for (; j < rem; j++) {
            int sj = __shfl_sync(0xffffffffu, s, j);
            float4 v = base[(size_t)sj * 32 + lane];
            acc.x += v.x; acc.y += v.y; acc.z += v.z; acc.w += v.w;
        }
    }
    float sc = d_dinv[d];
    float4 bb = (lane < 16) ? *(const float4*)(bmu + lane * 4)
                            : *(const float4*)(blv + (lane - 16) * 4);
    float4 r;
    r.x = acc.x * sc + bb.x; r.y = acc.y * sc + bb.y;
    r.z = acc.z * sc + bb.z; r.w = acc.w * sc + bb.w;
    float* p = (lane < 16) ? (mu + (size_t)d * OUTC + lane * 4)
                           : (lv + (size_t)d * OUTC + (lane - 16) * 4);
    *(float4*)p = r;
}

// ---------------- launch ----------------
extern "C" void kernel_launch(void* const* d_in, const int* in_sizes, int n_in,
                              void* d_out, int out_size) {
    const float* x   = (const float*)d_in[0];
    const int*   ei  = (const int*)d_in[1];     // int32 (JAX x64 disabled)
    const float* W1  = (const float*)d_in[2];
    const float* b1  = (const float*)d_in[3];
    const float* Wmu = (const float*)d_in[4];
    const float* bmu = (const float*)d_in[5];
    const float* Wlv = (const float*)d_in[6];
    const float* blv = (const float*)d_in[7];

    const int e = in_sizes[1] / 2;
    const int n = in_sizes[0] / INC;
    const int* src = ei;
    const int* dst = ei + e;

    float* mu = (float*)d_out;
    float* lv = mu + (size_t)n * OUTC;

    float *hs_p, *h1_p, *gs_p, *w1c_p, *wcat_p, *dinv_p;
    cudaGetSymbolAddress((void**)&hs_p,   d_Hs);
    cudaGetSymbolAddress((void**)&h1_p,   d_H1);
    cudaGetSymbolAddress((void**)&gs_p,   d_Gs);
    cudaGetSymbolAddress((void**)&w1c_p,  d_W1c);
    cudaGetSymbolAddress((void**)&wcat_p, d_Wcat);
    cudaGetSymbolAddress((void**)&dinv_p, d_dinv);

    static cudaStream_t s1 = nullptr;
    static cudaEvent_t  evFork = nullptr, evW = nullptr, evJoin = nullptr;
    if (!s1) {
        cudaStreamCreateWithFlags(&s1, cudaStreamNonBlocking);
        cudaEventCreateWithFlags(&evFork, cudaEventDisableTiming);
        cudaEventCreateWithFlags(&evW, cudaEventDisableTiming);
        cudaEventCreateWithFlags(&evJoin, cudaEventDisableTiming);
        cudaFuncSetAttribute(k_gemm<INC>,
            cudaFuncAttributeMaxDynamicSharedMemorySize, GEMM_SMEM);
        cudaFuncSetAttribute(k_gemm<HID>,
            cudaFuncAttributeMaxDynamicSharedMemorySize, GEMM_SMEM);
    }

    const int T = 256;
    const int nblk = (n + SCAN_B - 1) / SCAN_B;
    const int gblk = (n + 127) / 128;

    // fork: graph prep on s1 concurrent with GEMM1 on main stream.
    // Launch order keeps GEMM1 at slot 4 for ncu capture.
    cudaEventRecord(evFork, 0);
    cudaStreamWaitEvent(s1, evFork, 0);

    k_cvt_w1<<<(INC * HID + T - 1) / T, T, 0, s1>>>(W1);   // 1
    cudaEventRecord(evW, s1);                              // W1c ready
    k_zero_deg<<<(n + T - 1) / T, T, 0, s1>>>(n);          // 2
    k_degcnt<<<(e + T - 1) / T, T, 0, s1>>>(dst, e);       // 3

    // GEMM1 (tf32 tensor cores, pre-converted B) — 4th launch (profiled)
    cudaStreamWaitEvent(0, evW, 0);
    k_gemm<INC><<<gblk, 256, GEMM_SMEM>>>(x, w1c_p, hs_p, nullptr, n);

    k_dinv<<<(n + T - 1) / T, T, 0, s1>>>(n);
    k_scanA<<<nblk, SCAN_B, 0, s1>>>(n);
    k_scanB<<<1, MAXBLK, 0, s1>>>(nblk);
    k_scanC<<<nblk, SCAN_B, 0, s1>>>(n);
    k_scatter<<<(e + T - 1) / T, T, 0, s1>>>(src, dst, e);
    k_build_wcat<<<(HID * HID + T - 1) / T, T, 0, s1>>>(Wmu, Wlv);

    // join
    cudaEventRecord(evJoin, s1);
    cudaStreamWaitEvent(0, evJoin, 0);

    // agg1 (folds all dinv scaling), GEMM2 (tf32, pre-converted B), agg2
    k_agg1<<<(n * 32 + T - 1) / T, T>>>(b1, n);
    k_gemm<HID><<<gblk, 256, GEMM_SMEM>>>(h1_p, wcat_p, gs_p, dinv_p, n);
    k_agg2<<<(n * 32 + T - 1) / T, T>>>(bmu, blv, mu, lv, n);
}

// round 17
// speedup vs baseline: 1.1928x; 1.0807x over previous
#include <cuda_runtime.h>
#include <cuda_fp16.h>
#include <cstdint>

#define NN   100000
#define EE   1600000
#define INC  256
#define HID  128
#define OUTC 64
#define SCAN_B 128
#define MAXBLK 1024

// -------- scratch (__device__ globals; allocation is forbidden) --------
static __device__ __align__(256) int    d_degi[NN];
static __device__ __align__(256) int    d_off [NN + 1];
static __device__ __align__(256) int    d_cur [NN];
static __device__ __align__(256) int    d_csr [EE];
static __device__ __align__(256) int    d_bsum [MAXBLK];
static __device__ __align__(256) int    d_bsum2[MAXBLK];
static __device__ __align__(256) float  d_dinv[NN];
static __device__ __align__(256) __half d_HsH[(size_t)NN * HID];  // x@W1, fp16
static __device__ __align__(256) float  d_H1 [(size_t)NN * HID];  // leaky(agg1) fp32
static __device__ __align__(256) __half d_GsH[(size_t)NN * HID];  // dinv*(H1@Wcat) fp16
static __device__ __align__(256) float  d_W1c [INC * HID];        // W1 pre-cvt tf32
static __device__ __align__(256) float  d_Wcat[HID * HID];        // [Wmu|Wlv] tf32

// ---------------- tf32 / fp16 / async helpers ----------------
static __device__ __forceinline__ uint32_t f2tf32(float f) {
    uint32_t r;
    asm("cvt.rna.tf32.f32 %0, %1;" : "=r"(r) : "f"(f));
    return r;
}
static __device__ __forceinline__ void mma_tf32_16x8x8(
    float& c0, float& c1, float& c2, float& c3,
    uint32_t a0, uint32_t a1, uint32_t a2, uint32_t a3,
    uint32_t b0, uint32_t b1) {
    asm volatile(
        "mma.sync.aligned.m16n8k8.row.col.f32.tf32.tf32.f32 "
        "{%0,%1,%2,%3}, {%4,%5,%6,%7}, {%8,%9}, {%0,%1,%2,%3};"
        : "+f"(c0), "+f"(c1), "+f"(c2), "+f"(c3)
        : "r"(a0), "r"(a1), "r"(a2), "r"(a3), "r"(b0), "r"(b1));
}
static __device__ __forceinline__ void cp16(void* smem_dst, const void* gsrc) {
    uint32_t s = (uint32_t)__cvta_generic_to_shared(smem_dst);
    asm volatile("cp.async.ca.shared.global [%0], [%1], 16;"
                 :: "r"(s), "l"(gsrc) : "memory");
}
static __device__ __forceinline__ void cp_commit() {
    asm volatile("cp.async.commit_group;" ::: "memory");
}
static __device__ __forceinline__ void cp_wait0() {
    asm volatile("cp.async.wait_group 0;" ::: "memory");
}
// 4 halves (uint2) -> float4
static __device__ __forceinline__ float4 h4_to_f4(uint2 u) {
    __half2 a = *(__half2*)&u.x;
    __half2 b = *(__half2*)&u.y;
    float2 fa = __half22float2(a), fb = __half22float2(b);
    return make_float4(fa.x, fa.y, fb.x, fb.y);
}

// ---------------- graph preprocessing ----------------
__global__ void k_cvt_w1(const float* __restrict__ W1) {
    int i = blockIdx.x * blockDim.x + threadIdx.x;   // INC*HID = 32768
    if (i < INC * HID)
        ((uint32_t*)d_W1c)[i] = f2tf32(W1[i]);
}
__global__ void k_zero_deg(int n) {
    int i = blockIdx.x * blockDim.x + threadIdx.x;
    if (i < n) d_degi[i] = 0;
}
__global__ void k_degcnt(const int* __restrict__ dst, int e) {
    int i = blockIdx.x * blockDim.x + threadIdx.x;
    if (i < e) atomicAdd(&d_degi[dst[i]], 1);
}
__global__ void k_dinv(int n) {
    int i = blockIdx.x * blockDim.x + threadIdx.x;
    if (i < n) d_dinv[i] = rsqrtf((float)(d_degi[i] + 1));  // +1 self loop
}
__global__ void k_scanA(int n) {
    __shared__ int sm[SCAN_B];
    int b = blockIdx.x, t = threadIdx.x, gi = b * SCAN_B + t;
    int v = (gi < n) ? d_degi[gi] : 0;
    sm[t] = v; __syncthreads();
    #pragma unroll
    for (int s = 1; s < SCAN_B; s <<= 1) {
        int u = (t >= s) ? sm[t - s] : 0;
        __syncthreads(); sm[t] += u; __syncthreads();
    }
    if (gi < n) d_off[gi + 1] = sm[t];
    if (t == SCAN_B - 1) d_bsum[b] = sm[t];
}
__global__ void k_scanB(int nblk) {
    __shared__ int sm[MAXBLK];
    int t = threadIdx.x;
    int v = (t < nblk) ? d_bsum[t] : 0;
    sm[t] = v; __syncthreads();
    #pragma unroll
    for (int s = 1; s < MAXBLK; s <<= 1) {
        int u = (t >= s) ? sm[t - s] : 0;
        __syncthreads(); sm[t] += u; __syncthreads();
    }
    if (t < nblk) d_bsum2[t] = sm[t] - v;
    if (t == 0) d_off[0] = 0;
}
__global__ void k_scanC(int n) {
    int b = blockIdx.x, t = threadIdx.x, gi = b * SCAN_B + t;
    if (gi < n) {
        int o = d_off[gi + 1] + d_bsum2[b];
        d_off[gi + 1] = o;
        d_cur[gi] = o - d_degi[gi];
    }
}
__global__ void k_scatter(const int* __restrict__ src,
                          const int* __restrict__ dst, int e) {
    int i = blockIdx.x * blockDim.x + threadIdx.x;
    if (i < e) {
        int d = dst[i];
        int pos = atomicAdd(&d_cur[d], 1);
        d_csr[pos] = src[i];
    }
}
__global__ void k_build_wcat(const float* __restrict__ Wmu,
                             const float* __restrict__ Wlv) {
    int i = blockIdx.x * blockDim.x + threadIdx.x;
    if (i < HID * HID) {
        int k = i / HID, c = i % HID;
        float v = (c < OUTC) ? Wmu[k * OUTC + c] : Wlv[k * OUTC + (c - OUTC)];
        ((uint32_t*)d_Wcat)[i] = f2tf32(v);      // pre-converted tf32 bits
    }
}

// -------- tf32 tensor-core GEMM: Chalf[M,128] = A[M,K] @ Btf32[K,128] [*dinv] --------
// 256 thr = 8 warps (2M x 4N), warp tile 64x32, BK=32, 2-stage.
// A: LDG->cvt->STS. B: pre-converted tf32 via cp.async, plain LDS fragments.
// Output written as fp16 (half2), dinv scale applied before rounding.
template <int K>
__global__ void __launch_bounds__(256)
k_gemm(const float* __restrict__ A, const float* __restrict__ B,
       __half* __restrict__ C, const float* __restrict__ dinv, int M) {
    constexpr int BM = 128, BN = 128, BK = 32;
    constexpr int NIT = K / BK;
    constexpr int ASTR = 36, BSTR = 136;
    extern __shared__ uint32_t dyn[];
    uint32_t* sA = dyn;                         // 2 x 128 x 36
    uint32_t* sB = dyn + 2 * BM * ASTR;         // 2 x 32 x 136

    const int tid  = threadIdx.x;
    const int lane = tid & 31;
    const int wid  = tid >> 5;
    const int wm   = wid & 1;
    const int wn   = wid >> 1;
    const int gid  = lane >> 2;
    const int tq   = lane & 3;
    const int row0 = blockIdx.x * BM;

    float4 av[4];
    auto gloadA = [&](int it) {
        int k0 = it * BK;
        #pragma unroll
        for (int i = 0; i < 4; i++) {
            int idx = tid + i * 256;
            int r = idx >> 3, c0 = (idx & 7) * 4;
            int gr = row0 + r;
            av[i] = (gr < M)
                ? *(const float4*)(A + (size_t)gr * K + k0 + c0)
                : make_float4(0.f, 0.f, 0.f, 0.f);
        }
    };
    auto stsA = [&](int b) {
        #pragma unroll
        for (int i = 0; i < 4; i++) {
            int idx = tid + i * 256;
            int r = idx >> 3, c0 = (idx & 7) * 4;
            uint4 t = make_uint4(f2tf32(av[i].x), f2tf32(av[i].y),
                                 f2tf32(av[i].z), f2tf32(av[i].w));
            *(uint4*)&sA[b * BM * ASTR + r * ASTR + c0] = t;
        }
    };
    auto cpB = [&](int it, int b) {
        #pragma unroll
        for (int i = 0; i < 4; i++) {
            int idx = tid + i * 256;
            int r = idx >> 5, c0 = (idx & 31) * 4;
            cp16(&sB[b * BK * BSTR + r * BSTR + c0],
                 B + (size_t)(it * BK + r) * BN + c0);
        }
        cp_commit();
    };

    float acc[4][4][4] = {};

    gloadA(0);
    cpB(0, 0);
    stsA(0);
    cp_wait0();
    __syncthreads();

    int buf = 0;
    for (int it = 0; it < NIT; it++) {
        if (it + 1 < NIT) {
            gloadA(it + 1);
            cpB(it + 1, buf ^ 1);
        }
        const uint32_t* pa = &sA[buf * BM * ASTR];
        const uint32_t* pb = &sB[buf * BK * BSTR];
        #pragma unroll
        for (int ks = 0; ks < 4; ks++) {
            const int kk = ks * 8;
            uint32_t af[4][4], bf[4][2];
            #pragma unroll
            for (int mt = 0; mt < 4; mt++) {
                int m = wm * 64 + mt * 16 + gid;
                af[mt][0] = pa[(m    ) * ASTR + kk + tq];
                af[mt][1] = pa[(m + 8) * ASTR + kk + tq];
                af[mt][2] = pa[(m    ) * ASTR + kk + tq + 4];
                af[mt][3] = pa[(m + 8) * ASTR + kk + tq + 4];
            }
            #pragma unroll
            for (int nt = 0; nt < 4; nt++) {
                int nn = wn * 32 + nt * 8 + gid;
                bf[nt][0] = pb[(kk + tq    ) * BSTR + nn];   // already tf32
                bf[nt][1] = pb[(kk + tq + 4) * BSTR + nn];
            }
            #pragma unroll
            for (int mt = 0; mt < 4; mt++)
                #pragma unroll
                for (int nt = 0; nt < 4; nt++)
                    mma_tf32_16x8x8(acc[mt][nt][0], acc[mt][nt][1],
                                    acc[mt][nt][2], acc[mt][nt][3],
                                    af[mt][0], af[mt][1], af[mt][2], af[mt][3],
                                    bf[nt][0], bf[nt][1]);
        }
        if (it + 1 < NIT) {
            stsA(buf ^ 1);
            cp_wait0();
        }
        __syncthreads();
        buf ^= 1;
    }

    #pragma unroll
    for (int mt = 0; mt < 4; mt++) {
        int ra = row0 + wm * 64 + mt * 16 + gid;
        int rb = ra + 8;
        #pragma unroll
        for (int nt = 0; nt < 4; nt++) {
            int col = wn * 32 + nt * 8 + 2 * tq;
            if (ra < M) {
                float s = dinv ? dinv[ra] : 1.0f;
                *(__half2*)(C + (size_t)ra * BN + col) =
                    __floats2half2_rn(acc[mt][nt][0] * s, acc[mt][nt][1] * s);
            }
            if (rb < M) {
                float s = dinv ? dinv[rb] : 1.0f;
                *(__half2*)(C + (size_t)rb * BN + col) =
                    __floats2half2_rn(acc[mt][nt][2] * s, acc[mt][nt][3] * s);
            }
        }
    }
}

#define GEMM_SMEM ((2 * 128 * 36 + 2 * 32 * 136) * 4)   // 71680 B

// -------- agg1: warp per node, fp16 gather (8B/lane), fp32 accumulate --------
// H1[d] = leaky( dinv[d]*( Σ dinv[s]*HsH[s] + dinv[d]*HsH[d] ) + b1 )  (fp32 out)
__global__ void k_agg1(const float* __restrict__ b1, int n) {
    int d = (blockIdx.x * blockDim.x + threadIdx.x) >> 5;
    int lane = threadIdx.x & 31;
    if (d >= n) return;
    const __half* bh = d_HsH;
    float sd = d_dinv[d];
    float4 self = h4_to_f4(*(const uint2*)(bh + (size_t)d * HID + lane * 4));
    float4 acc = make_float4(self.x * sd, self.y * sd, self.z * sd, self.w * sd);
    int beg = d_off[d], end = d_off[d + 1];
    for (int k = beg; k < end; k += 32) {
        int rem = end - k; if (rem > 32) rem = 32;
        int   s  = (lane < rem) ? d_csr[k + lane] : 0;
        float sv = (lane < rem) ? d_dinv[s] : 0.f;
        int j = 0;
        for (; j + 4 <= rem; j += 4) {
            int s0 = __shfl_sync(0xffffffffu, s, j);
            int s1 = __shfl_sync(0xffffffffu, s, j + 1);
            int s2 = __shfl_sync(0xffffffffu, s, j + 2);
            int s3 = __shfl_sync(0xffffffffu, s, j + 3);
            float d0 = __shfl_sync(0xffffffffu, sv, j);
            float d1 = __shfl_sync(0xffffffffu, sv, j + 1);
            float d2 = __shfl_sync(0xffffffffu, sv, j + 2);
            float d3 = __shfl_sync(0xffffffffu, sv, j + 3);
            uint2 u0 = *(const uint2*)(bh + (size_t)s0 * HID + lane * 4);
            uint2 u1 = *(const uint2*)(bh + (size_t)s1 * HID + lane * 4);
            uint2 u2 = *(const uint2*)(bh + (size_t)s2 * HID + lane * 4);
            uint2 u3 = *(const uint2*)(bh + (size_t)s3 * HID + lane * 4);
            float4 v0 = h4_to_f4(u0), v1 = h4_to_f4(u1);
            float4 v2 = h4_to_f4(u2), v3 = h4_to_f4(u3);
            acc.x += v0.x * d0 + v1.x * d1 + v2.x * d2 + v3.x * d3;
            acc.y += v0.y * d0 + v1.y * d1 + v2.y * d2 + v3.y * d3;
            acc.z += v0.z * d0 + v1.z * d1 + v2.z * d2 + v3.z * d3;
            acc.w += v0.w * d0 + v1.w * d1 + v2.w * d2 + v3.w * d3;
        }
        for (; j < rem; j++) {
            int   sj = __shfl_sync(0xffffffffu, s,  j);
            float dv = __shfl_sync(0xffffffffu, sv, j);
            float4 v = h4_to_f4(*(const uint2*)(bh + (size_t)sj * HID + lane * 4));
            acc.x += v.x * dv; acc.y += v.y * dv;
            acc.z += v.z * dv; acc.w += v.w * dv;
        }
    }
    float4 bb = *(const float4*)(b1 + lane * 4);
    float4 r;
    r.x = acc.x * sd + bb.x; r.y = acc.y * sd + bb.y;
    r.z = acc.z * sd + bb.z; r.w = acc.w * sd + bb.w;
    r.x = r.x >= 0.f ? r.x : 0.01f * r.x;
    r.y = r.y >= 0.f ? r.y : 0.01f * r.y;
    r.z = r.z >= 0.f ? r.z : 0.01f * r.z;
    r.w = r.w >= 0.f ? r.w : 0.01f * r.w;
    *(float4*)(d_H1 + (size_t)d * HID + lane * 4) = r;
}

// -------- agg2: warp per node, fp16 gather, GsH pre-scaled, fp32 out --------
__global__ void k_agg2(const float* __restrict__ bmu,
                       const float* __restrict__ blv,
                       float* __restrict__ mu, float* __restrict__ lv, int n) {
    int d = (blockIdx.x * blockDim.x + threadIdx.x) >> 5;
    int lane = threadIdx.x & 31;
    if (d >= n) return;
    const __half* bh = d_GsH;
    float4 acc = h4_to_f4(*(const uint2*)(bh + (size_t)d * HID + lane * 4)); // self
    int beg = d_off[d], end = d_off[d + 1];
    for (int k = beg; k < end; k += 32) {
        int rem = end - k; if (rem > 32) rem = 32;
        int s = (lane < rem) ? d_csr[k + lane] : 0;
        int j = 0;
        for (; j + 4 <= rem; j += 4) {
            int s0 = __shfl_sync(0xffffffffu, s, j);
            int s1 = __shfl_sync(0xffffffffu, s, j + 1);
            int s2 = __shfl_sync(0xffffffffu, s, j + 2);
            int s3 = __shfl_sync(0xffffffffu, s, j + 3);
            uint2 u0 = *(const uint2*)(bh + (size_t)s0 * HID + lane * 4);
            uint2 u1 = *(const uint2*)(bh + (size_t)s1 * HID + lane * 4);
            uint2 u2 = *(const uint2*)(bh + (size_t)s2 * HID + lane * 4);
            uint2 u3 = *(const uint2*)(bh + (size_t)s3 * HID + lane * 4);
            float4 v0 = h4_to_f4(u0), v1 = h4_to_f4(u1);
            float4 v2 = h4_to_f4(u2), v3 = h4_to_f4(u3);
            acc.x += v0.x + v1.x + v2.x + v3.x;
            acc.y += v0.y + v1.y + v2.y + v3.y;
            acc.z += v0.z + v1.z + v2.z + v3.z;
            acc.w += v0.w + v1.w + v2.w + v3.w;
        }
        for (; j < rem; j++) {
            int sj = __shfl_sync(0xffffffffu, s, j);
            float4 v = h4_to_f4(*(const uint2*)(bh + (size_t)sj * HID + lane * 4));
            acc.x += v.x; acc.y += v.y; acc.z += v.z; acc.w += v.w;
        }
    }
    float sc = d_dinv[d];
    float4 bb = (lane < 16) ? *(const float4*)(bmu + lane * 4)
                            : *(const float4*)(blv + (lane - 16) * 4);
    float4 r;
    r.x = acc.x * sc + bb.x; r.y = acc.y * sc + bb.y;
    r.z = acc.z * sc + bb.z; r.w = acc.w * sc + bb.w;
    float* p = (lane < 16) ? (mu + (size_t)d * OUTC + lane * 4)
                           : (lv + (size_t)d * OUTC + (lane - 16) * 4);
    *(float4*)p = r;
}

// ---------------- launch ----------------
extern "C" void kernel_launch(void* const* d_in, const int* in_sizes, int n_in,
                              void* d_out, int out_size) {
    const float* x   = (const float*)d_in[0];
    const int*   ei  = (const int*)d_in[1];     // int32 (JAX x64 disabled)
    const float* W1  = (const float*)d_in[2];
    const float* b1  = (const float*)d_in[3];
    const float* Wmu = (const float*)d_in[4];
    const float* bmu = (const float*)d_in[5];
    const float* Wlv = (const float*)d_in[6];
    const float* blv = (const float*)d_in[7];

    const int e = in_sizes[1] / 2;
    const int n = in_sizes[0] / INC;
    const int* src = ei;
    const int* dst = ei + e;

    float* mu = (float*)d_out;
    float* lv = mu + (size_t)n * OUTC;

    __half *hsh_p, *gsh_p;
    float *h1_p, *w1c_p, *wcat_p, *dinv_p;
    cudaGetSymbolAddress((void**)&hsh_p, d_HsH);
    cudaGetSymbolAddress((void**)&h1_p,  d_H1);
    cudaGetSymbolAddress((void**)&gsh_p, d_GsH);
    cudaGetSymbolAddress((void**)&w1c_p, d_W1c);
    cudaGetSymbolAddress((void**)&wcat_p, d_Wcat);
    cudaGetSymbolAddress((void**)&dinv_p, d_dinv);

    static cudaStream_t s1 = nullptr;
    static cudaEvent_t  evFork = nullptr, evW = nullptr, evJoin = nullptr;
    if (!s1) {
        cudaStreamCreateWithFlags(&s1, cudaStreamNonBlocking);
        cudaEventCreateWithFlags(&evFork, cudaEventDisableTiming);
        cudaEventCreateWithFlags(&evW, cudaEventDisableTiming);
        cudaEventCreateWithFlags(&evJoin, cudaEventDisableTiming);
        cudaFuncSetAttribute(k_gemm<INC>,
            cudaFuncAttributeMaxDynamicSharedMemorySize, GEMM_SMEM);
        cudaFuncSetAttribute(k_gemm<HID>,
            cudaFuncAttributeMaxDynamicSharedMemorySize, GEMM_SMEM);
    }

    const int T = 256;
    const int nblk = (n + SCAN_B - 1) / SCAN_B;
    const int gblk = (n + 127) / 128;

    // fork: graph prep on s1 concurrent with GEMM1 on main stream.
    // Launch order keeps GEMM1 at slot 4 for ncu capture.
    cudaEventRecord(evFork, 0);
    cudaStreamWaitEvent(s1, evFork, 0);

    k_cvt_w1<<<(INC * HID + T - 1) / T, T, 0, s1>>>(W1);   // 1
    cudaEventRecord(evW, s1);                              // W1c ready
    k_zero_deg<<<(n + T - 1) / T, T, 0, s1>>>(n);          // 2
    k_degcnt<<<(e + T - 1) / T, T, 0, s1>>>(dst, e);       // 3

    // GEMM1 (tf32 tensor cores, fp16 output) — 4th launch (profiled)
    cudaStreamWaitEvent(0, evW, 0);
    k_gemm<INC><<<gblk, 256, GEMM_SMEM>>>(x, w1c_p, hsh_p, nullptr, n);

    k_dinv<<<(n + T - 1) / T, T, 0, s1>>>(n);
    k_scanA<<<nblk, SCAN_B, 0, s1>>>(n);
    k_scanB<<<1, MAXBLK, 0, s1>>>(nblk);
    k_scanC<<<nblk, SCAN_B, 0, s1>>>(n);
    k_scatter<<<(e + T - 1) / T, T, 0, s1>>>(src, dst, e);
    k_build_wcat<<<(HID * HID + T - 1) / T, T, 0, s1>>>(Wmu, Wlv);

    // join
    cudaEventRecord(evJoin, s1);
    cudaStreamWaitEvent(0, evJoin, 0);

    // agg1 (fp16 gather), GEMM2 (fp16 output, dinv-scaled), agg2 (fp16 gather)
    k_agg1<<<(n * 32 + T - 1) / T, T>>>(b1, n);
    k_gemm<HID><<<gblk, 256, GEMM_SMEM>>>(h1_p, wcat_p, gsh_p, dinv_p, n);
    k_agg2<<<(n * 32 + T - 1) / T, T>>>(bmu, blv, mu, lv, n);
}